// round 17
// baseline (speedup 1.0000x reference)
#include <cuda_runtime.h>
#include <cuda_fp16.h>
#include <stdint.h>

// Problem constants
#define MAXN 40000
#define MAXE 640000
#define NG   64
#define F    128
#define SCAN_TILE 1024
#define MAXNB ((MAXN + SCAN_TILE - 1) / SCAN_TILE)   // 40

// ---------------- device scratch (zero at load; each call restores zeros) --
__device__ __half          g_xh[(size_t)MAXN * F];   // fp16 ping
__device__ __half          g_hbuf[(size_t)MAXN * F]; // fp16 pong (prescaled)
__device__ int             g_deg[MAXN];              // MUST be 0 at entry
__device__ float           g_dis[MAXN];
__device__ int             g_rowptr[MAXN + 1];
__device__ int             g_tmp[MAXN];              // scan overwrites each call
__device__ unsigned short  g_csr[MAXE];              // u16 node ids (N < 65536)
__device__ float           g_gsum[NG];               // MUST be 0 at entry
__device__ float           g_gcnt[NG];               // MUST be 0 at entry
__device__ int             g_cnt1;                   // prep->scan gate; MUST be 0
__device__ int             g_cnt2;                   // agg3->final gate; MUST be 0

// -------- PDL intrinsics --------
__device__ __forceinline__ void gdc_launch() {
    asm volatile("griddepcontrol.launch_dependents;");
}
__device__ __forceinline__ void gdc_wait() {
    asm volatile("griddepcontrol.wait;" ::: "memory");
}

// ==== fused prep+scan: convert x, degree histogram, then scan (spin-gated) ==
// grid layout: [0,cBlocks) convert | [cBlocks,cBlocks+eBlocks) count |
//              [cBlocks+eBlocks, +nb) scan tiles (spin until counting done)
__global__ __launch_bounds__(SCAN_TILE)
void prep_scan_kernel(const float* __restrict__ x, int total4,
                      const int* __restrict__ col, int E, int n,
                      int cBlocks, int eBlocks, int nb) {
    gdc_launch();
    int tid = threadIdx.x;

    if (blockIdx.x < cBlocks) {
        // ---- convert x -> fp16 ----
        int i = blockIdx.x * SCAN_TILE + tid;
        if (i < total4) {
            float4 v = *(const float4*)(x + (size_t)i * 4);
            __half2 h0 = __floats2half2_rn(v.x, v.y);
            __half2 h1 = __floats2half2_rn(v.z, v.w);
            uint2 pk;
            pk.x = *reinterpret_cast<unsigned*>(&h0);
            pk.y = *reinterpret_cast<unsigned*>(&h1);
            *(uint2*)(g_xh + (size_t)i * 4) = pk;
        }
        return;
    }

    if (blockIdx.x < cBlocks + eBlocks) {
        // ---- degree histogram (REDG), 4 edges/thread ----
        int i = (blockIdx.x - cBlocks) * SCAN_TILE + tid;
        int e = i * 4;
        if (e + 4 <= E) {
            int4 c4 = *(const int4*)(col + e);
            atomicAdd(&g_deg[c4.x], 1);
            atomicAdd(&g_deg[c4.y], 1);
            atomicAdd(&g_deg[c4.z], 1);
            atomicAdd(&g_deg[c4.w], 1);
        } else {
            for (int q = e; q < E; q++) atomicAdd(&g_deg[col[q]], 1);
        }
        __threadfence();          // make REDGs visible before arriving
        __syncthreads();
        if (tid == 0) atomicAdd(&g_cnt1, 1);
        return;
    }

    // ---- scan tile (redundant-prefix form, proven round 16) ----
    const int tile = blockIdx.x - cBlocks - eBlocks;
    __shared__ int sh[32];
    int lane = tid & 31, wid = tid >> 5;

    if (tid == 0) {
        while (*((volatile int*)&g_cnt1) < eBlocks) {}
    }
    __syncthreads();
    __threadfence();

    const int blockStart = tile * SCAN_TILE;
    int local = 0;
    for (int i = tid; i < blockStart; i += SCAN_TILE)
        local += g_deg[i];
#pragma unroll
    for (int o = 16; o > 0; o >>= 1) local += __shfl_xor_sync(0xffffffffu, local, o);
    if (lane == 0) sh[wid] = local;
    __syncthreads();
    if (wid == 0) {
        int w = sh[lane];
#pragma unroll
        for (int o = 16; o > 0; o >>= 1) w += __shfl_xor_sync(0xffffffffu, w, o);
        if (lane == 0) sh[0] = w;
    }
    __syncthreads();
    const int base = sh[0];
    __syncthreads();   // sh reused below

    int i = blockStart + tid;
    int v = 0;
    if (i < n) {
        v = g_deg[i];                          // edges only
        g_dis[i] = rsqrtf((float)(v + 1));     // +1 = self loop (not in CSR)
    }
    int xx = v;
#pragma unroll
    for (int o = 1; o < 32; o <<= 1) {
        int y = __shfl_up_sync(0xffffffffu, xx, o);
        if (lane >= o) xx += y;
    }
    if (lane == 31) sh[wid] = xx;
    __syncthreads();
    if (wid == 0) {
        int w = sh[lane];
#pragma unroll
        for (int o = 1; o < 32; o <<= 1) {
            int y = __shfl_up_sync(0xffffffffu, w, o);
            if (lane >= o) w += y;
        }
        sh[lane] = w;
    }
    __syncthreads();
    int woff = (wid > 0) ? sh[wid - 1] : 0;
    if (i < n) {
        int rp = base + woff + xx - v;
        g_rowptr[i] = rp;
        g_tmp[i]    = rp;      // scatter's atomic cursor starts at rowptr
    }
    if (tile == nb - 1 && tid == 0)
        g_rowptr[n] = base + sh[31];
}

// ======== Tensor-core GEMM (fused with CSR scatter) ========
__device__ __forceinline__ void ldsm_x4(uint32_t* r, const __half* p) {
    uint32_t addr = (uint32_t)__cvta_generic_to_shared(p);
    asm volatile("ldmatrix.sync.aligned.m8n8.x4.shared.b16 {%0,%1,%2,%3}, [%4];"
                 : "=r"(r[0]), "=r"(r[1]), "=r"(r[2]), "=r"(r[3]) : "r"(addr));
}
__device__ __forceinline__ void ldsm_x2t(uint32_t* r, const __half* p) {
    uint32_t addr = (uint32_t)__cvta_generic_to_shared(p);
    asm volatile("ldmatrix.sync.aligned.m8n8.x2.trans.shared.b16 {%0,%1}, [%2];"
                 : "=r"(r[0]), "=r"(r[1]) : "r"(addr));
}
__device__ __forceinline__ void mma16816(float* c, const uint32_t* a, const uint32_t* b) {
    asm volatile("mma.sync.aligned.m16n8k16.row.col.f32.f16.f16.f32 "
                 "{%0,%1,%2,%3}, {%4,%5,%6,%7}, {%8,%9}, {%0,%1,%2,%3};"
                 : "+f"(c[0]), "+f"(c[1]), "+f"(c[2]), "+f"(c[3])
                 : "r"(a[0]), "r"(a[1]), "r"(a[2]), "r"(a[3]), "r"(b[0]), "r"(b[1]));
}

#define LDA 72   // 64 + 8 halves pad
#define LDB 136  // 128 + 8 halves pad

template <bool FUSE>
__global__ __launch_bounds__(256)
void gemm_tc_kernel(const float* __restrict__ W,
                    const float* __restrict__ bias, int M,
                    const int* __restrict__ erow,
                    const int* __restrict__ ecol, int E,
                    int nGemmBlocks) {
    __shared__ __half sA[128 * LDA];
    __shared__ __half sB[2][64 * LDB];
    __shared__ float sBias[128];

    gdc_launch();

    if (FUSE && blockIdx.x >= nGemmBlocks) {
        // scatter path (1 edge per thread) — proven round-13 form
        gdc_wait();
        if (blockIdx.x == nGemmBlocks && threadIdx.x == 0) g_cnt1 = 0; // reset gate
        int idx = (blockIdx.x - nGemmBlocks) * blockDim.x + threadIdx.x;
        if (idx < E) {
            int d = __ldg(ecol + idx);
            int s = __ldg(erow + idx);
            int p = atomicAdd(&g_tmp[d], 1);
            g_csr[p] = (unsigned short)s;
        }
        return;
    }

    const int t = threadIdx.x;
    const int wid = t >> 5, lane = t & 31;
    const int blockM = blockIdx.x * 128;
    const int warpM = (wid >> 1) * 32;
    const int warpN = (wid & 1) * 64;

    // PDL pre-wait: stage ALL of W + bias (external inputs)
    if (t < 128) sBias[t] = bias[t];
#pragma unroll
    for (int stage = 0; stage < 2; stage++) {
        const int kOff = stage * 64;
#pragma unroll
        for (int l = 0; l < 8; l++) {
            int idx = (t + l * 256) * 4;
            int row = idx >> 7;
            int col = idx & 127;
            float4 v = *(const float4*)(W + (size_t)(kOff + row) * 128 + col);
            __half2 h0 = __floats2half2_rn(v.x, v.y);
            __half2 h1 = __floats2half2_rn(v.z, v.w);
            uint2 pk;
            pk.x = *reinterpret_cast<unsigned*>(&h0);
            pk.y = *reinterpret_cast<unsigned*>(&h1);
            *(uint2*)(sB[stage] + row * LDB + col) = pk;
        }
    }

    float c[2][8][4];
#pragma unroll
    for (int mi = 0; mi < 2; mi++)
#pragma unroll
        for (int ni = 0; ni < 8; ni++)
#pragma unroll
            for (int q = 0; q < 4; q++) c[mi][ni][q] = 0.f;

    gdc_wait();   // g_xh / g_dis producers

#pragma unroll
    for (int stage = 0; stage < 2; stage++) {
        const int kOff = stage * 64;
#pragma unroll
        for (int l = 0; l < 4; l++) {
            int idx = (t + l * 256) * 8;
            int row = idx >> 6;
            int col = idx & 63;
            int grow = blockM + row;
            uint4 v = make_uint4(0u, 0u, 0u, 0u);
            if (grow < M)
                v = *(const uint4*)(g_xh + (size_t)grow * 128 + kOff + col);
            *(uint4*)(sA + row * LDA + col) = v;
        }
        __syncthreads();

#pragma unroll
        for (int ks = 0; ks < 4; ks++) {
            const int kb = ks * 16;
            uint32_t a[2][4];
#pragma unroll
            for (int mi = 0; mi < 2; mi++) {
                int r = warpM + mi * 16 + (lane & 15);
                int cc = kb + ((lane >> 4) << 3);
                ldsm_x4(a[mi], sA + r * LDA + cc);
            }
#pragma unroll
            for (int ni = 0; ni < 8; ni++) {
                uint32_t b[2];
                int r = kb + (lane & 15);
                int cc = warpN + ni * 8;
                ldsm_x2t(b, sB[stage] + r * LDB + cc);
                mma16816(c[0][ni], a[0], b);
                mma16816(c[1][ni], a[1], b);
            }
        }
        __syncthreads();
    }

#pragma unroll
    for (int mi = 0; mi < 2; mi++) {
        int rBase = blockM + warpM + mi * 16 + (lane >> 2);
#pragma unroll
        for (int hh = 0; hh < 2; hh++) {
            int r = rBase + hh * 8;
            if (r < M) {
                float ds = g_dis[r];
#pragma unroll
                for (int ni = 0; ni < 8; ni++) {
                    int col = warpN + ni * 8 + (lane & 3) * 2;
                    float v0 = (c[mi][ni][hh * 2 + 0] + sBias[col]) * ds;
                    float v1 = (c[mi][ni][hh * 2 + 1] + sBias[col + 1]) * ds;
                    __half2 hv = __floats2half2_rn(v0, v1);
                    *(__half2*)(g_hbuf + (size_t)r * 128 + col) = hv;
                }
            }
        }
    }
}

// ======== CSR gather aggregation (fp16 rows, fp32 accumulate) ========
__device__ __forceinline__ void accum_row(float acc[4], const __half* rowp, int lane) {
    uint2 u = *(const uint2*)(rowp + lane * 4);
    __half2 h0 = *reinterpret_cast<__half2*>(&u.x);
    __half2 h1 = *reinterpret_cast<__half2*>(&u.y);
    float2 f0 = __half22float2(h0);
    float2 f1 = __half22float2(h1);
    acc[0] += f0.x; acc[1] += f0.y; acc[2] += f1.x; acc[3] += f1.y;
}

template <bool POOL>
__global__ __launch_bounds__(512)
void aggregate_kernel(int n, const int* __restrict__ batch,
                      const float* __restrict__ Wl,
                      float* __restrict__ out, const float* __restrict__ bl,
                      int nBlocks) {
    gdc_launch();
    gdc_wait();
    int node = blockIdx.x * 16 + (threadIdx.x >> 5);
    int lane = threadIdx.x & 31;
    bool active = (node < n);

    if (active) {
        const __half* __restrict__ h = g_hbuf;
        int s = g_rowptr[node];
        int e = g_rowptr[node + 1];
        float acc[4] = {0.f, 0.f, 0.f, 0.f};

        accum_row(acc, h + (size_t)node * 128, lane);   // self loop

        int p = s;
        for (; p + 4 <= e; p += 4) {
            int si[4];
#pragma unroll
            for (int q = 0; q < 4; q++) si[q] = (int)g_csr[p + q];
#pragma unroll
            for (int q = 0; q < 4; q++)
                accum_row(acc, h + (size_t)si[q] * 128, lane);
        }
        for (; p < e; p++)
            accum_row(acc, h + (size_t)(int)g_csr[p] * 128, lane);

        float dd = g_dis[node];
#pragma unroll
        for (int j = 0; j < 4; j++) acc[j] = fmaxf(acc[j] * dd, 0.f);

        if (POOL) {
            float4 w = *(const float4*)(Wl + lane * 4);
            float sv = acc[0] * w.x + acc[1] * w.y + acc[2] * w.z + acc[3] * w.w;
#pragma unroll
            for (int o = 16; o > 0; o >>= 1) sv += __shfl_xor_sync(0xffffffffu, sv, o);
            if (lane == 0) {
                unsigned b = (unsigned)batch[node];
                if (b < NG) {
                    atomicAdd(&g_gsum[b], sv);
                    atomicAdd(&g_gcnt[b], 1.0f);
                }
            }
        } else {
            __half2 o0 = __floats2half2_rn(acc[0], acc[1]);
            __half2 o1 = __floats2half2_rn(acc[2], acc[3]);
            uint2 pk;
            pk.x = *reinterpret_cast<unsigned*>(&o0);
            pk.y = *reinterpret_cast<unsigned*>(&o1);
            *(uint2*)(g_xh + (size_t)node * 128 + lane * 4) = pk;
            if (lane == 0) g_deg[node] = 0;   // restore zero-state
        }
    }

    if (POOL) {
        // ---- last-block final: out = gsum/gcnt + bl ----
        __shared__ int sLast;
        __threadfence();
        __syncthreads();
        if (threadIdx.x == 0) {
            int v = atomicAdd(&g_cnt2, 1);
            sLast = (v == nBlocks - 1) ? 1 : 0;
        }
        __syncthreads();
        if (sLast) {
            __threadfence();
            int g = threadIdx.x;
            if (g < NG) {
                out[g] = g_gsum[g] / fmaxf(g_gcnt[g], 1.0f) + bl[0];
                g_gsum[g] = 0.f;
                g_gcnt[g] = 0.f;
            }
            if (threadIdx.x == 0) g_cnt2 = 0;
        }
    }
}

// --------------------------------------------------------------------------
template <typename... Args>
static void launch_pdl(void (*kern)(Args...), dim3 grid, dim3 block,
                       Args... args) {
    cudaLaunchConfig_t cfg = {};
    cfg.gridDim = grid;
    cfg.blockDim = block;
    cudaLaunchAttribute attr[1];
    attr[0].id = cudaLaunchAttributeProgrammaticStreamSerialization;
    attr[0].val.programmaticStreamSerializationAllowed = 1;
    cfg.attrs = attr;
    cfg.numAttrs = 1;
    cudaLaunchKernelEx(&cfg, kern, args...);
}

extern "C" void kernel_launch(void* const* d_in, const int* in_sizes, int n_in,
                              void* d_out, int out_size) {
    const float* x     = (const float*)d_in[0];
    const int*   eidx  = (const int*)d_in[1];
    const int*   batch = (const int*)d_in[2];

    int wbase = (in_sizes[3] < 128) ? 4 : 3;
    const float* W1 = (const float*)d_in[wbase + 0];
    const float* b1 = (const float*)d_in[wbase + 1];
    const float* W2 = (const float*)d_in[wbase + 2];
    const float* b2 = (const float*)d_in[wbase + 3];
    const float* W3 = (const float*)d_in[wbase + 4];
    const float* b3 = (const float*)d_in[wbase + 5];
    const float* Wl = (const float*)d_in[wbase + 6];
    const float* bl = (const float*)d_in[wbase + 7];
    float* out = (float*)d_out;

    const int N = in_sizes[0] / F;          // 40000
    const int E = in_sizes[1] / 2;          // 640000
    const int* erow = eidx;
    const int* ecol = eidx + E;
    const int NB = (N + SCAN_TILE - 1) / SCAN_TILE;

    const int total4   = N * F / 4;                                  // 1.28M
    const int cBlocks  = (total4 + SCAN_TILE - 1) / SCAN_TILE;       // 1250
    const int eBlocks  = ((E + 3) / 4 + SCAN_TILE - 1) / SCAN_TILE;  // 157
    const int sBlocks  = (E + 255) / 256;                            // scatter

    const int gemmBlocks = (N + 127) / 128;
    const int aggBlocks  = (N + 15) / 16;

    // fused prep (convert + count) + scan, spin-gated inside one kernel
    prep_scan_kernel<<<cBlocks + eBlocks + NB, SCAN_TILE>>>(
        x, total4, ecol, E, N, cBlocks, eBlocks, NB);

    // layer 1: GEMM fused with edge scatter
    launch_pdl(gemm_tc_kernel<true>, dim3(gemmBlocks + sBlocks), dim3(256),
               W1, b1, N, erow, ecol, E, gemmBlocks);
    launch_pdl(aggregate_kernel<false>, dim3(aggBlocks), dim3(512),
               N, batch, Wl, out, bl, aggBlocks);
    // layer 2
    launch_pdl(gemm_tc_kernel<false>, dim3(gemmBlocks), dim3(256),
               W2, b2, N, erow, ecol, E, gemmBlocks);
    launch_pdl(aggregate_kernel<false>, dim3(aggBlocks), dim3(512),
               N, batch, Wl, out, bl, aggBlocks);
    // layer 3 (+ fused global mean pool + fused final output)
    launch_pdl(gemm_tc_kernel<false>, dim3(gemmBlocks), dim3(256),
               W3, b3, N, erow, ecol, E, gemmBlocks);
    launch_pdl(aggregate_kernel<true>, dim3(aggBlocks), dim3(512),
               N, batch, Wl, out, bl, aggBlocks);
}